// round 16
// baseline (speedup 1.0000x reference)
#include <cuda_runtime.h>
#include <cuda_fp16.h>
#include <cstdint>
#include <math.h>

// Problem constants
#define Bn 4
#define Sn 2048
#define Dn 2048
#define Hn 16
#define DHn 128
#define TDn 6144            // 3*D
#define NROWS (Bn*Sn)       // 8192

#define ATTN_SCALE 0.08838834764831845f

// Scratch (device globals; no cudaMalloc allowed)
__device__ __half g_qkv[(size_t)NROWS * TDn];   // 100 MB half (RoPE'd, q scaled)
__device__ __half g_y[(size_t)NROWS * Dn];      // 33 MB  half (attn out)
__device__ __half g_xt[(size_t)NROWS * Dn];     // 33 MB  x  half
__device__ __half g_wq[(size_t)TDn * Dn];       // 25 MB  qkv_w half
__device__ __half g_wo[(size_t)Dn * Dn];        // 8 MB   out_w half
__device__ float2 g_rope[(size_t)Sn * 64];      // 1 MB   (cos,sin)[s][d2]

__device__ __forceinline__ void mma_f16(float* d,
                                        uint32_t a0, uint32_t a1,
                                        uint32_t a2, uint32_t a3,
                                        uint32_t b0, uint32_t b1) {
    asm volatile(
        "mma.sync.aligned.m16n8k16.row.col.f32.f16.f16.f32 "
        "{%0,%1,%2,%3}, {%4,%5,%6,%7}, {%8,%9}, {%0,%1,%2,%3};"
        : "+f"(d[0]), "+f"(d[1]), "+f"(d[2]), "+f"(d[3])
        : "r"(a0), "r"(a1), "r"(a2), "r"(a3), "r"(b0), "r"(b1));
}

__device__ __forceinline__ void ldsm4(uint32_t& r0, uint32_t& r1,
                                      uint32_t& r2, uint32_t& r3,
                                      const __half* p) {
    uint32_t a = (uint32_t)__cvta_generic_to_shared(p);
    asm volatile(
        "ldmatrix.sync.aligned.m8n8.x4.shared.b16 {%0,%1,%2,%3}, [%4];"
        : "=r"(r0), "=r"(r1), "=r"(r2), "=r"(r3) : "r"(a));
}

__device__ __forceinline__ void ldsm4t(uint32_t& r0, uint32_t& r1,
                                       uint32_t& r2, uint32_t& r3,
                                       const __half* p) {
    uint32_t a = (uint32_t)__cvta_generic_to_shared(p);
    asm volatile(
        "ldmatrix.sync.aligned.m8n8.x4.trans.shared.b16 {%0,%1,%2,%3}, [%4];"
        : "=r"(r0), "=r"(r1), "=r"(r2), "=r"(r3) : "r"(a));
}

__device__ __forceinline__ void cp16(void* smem_ptr, const void* gptr) {
    uint32_t sa = (uint32_t)__cvta_generic_to_shared(smem_ptr);
    asm volatile("cp.async.cg.shared.global [%0], [%1], 16;"
                 :: "r"(sa), "l"(gptr));
}
#define CP_COMMIT() asm volatile("cp.async.commit_group;" ::: "memory")
#define CP_WAIT(n)  asm volatile("cp.async.wait_group %0;" :: "n"(n) : "memory")

// ---------------------------------------------------------------------------
// Pre-convert fp32 -> fp16 (segmented, one launch) + fill RoPE table.
// ---------------------------------------------------------------------------
#define ROPE_N (Sn * 64)

__global__ __launch_bounds__(256) void conv_all_kernel(
    const float* __restrict__ x,  __half* __restrict__ xt,  int n8x,
    const float* __restrict__ wq, __half* __restrict__ wqh, int n8q,
    const float* __restrict__ wo, __half* __restrict__ woh, int n8o,
    float2* __restrict__ rope)
{
    int i = blockIdx.x * blockDim.x + threadIdx.x;
    const int nconv = n8x + n8q + n8o;
    if (i >= nconv) {
        int r = i - nconv;
        if (r < ROPE_N) {
            int s  = r >> 6;
            int d2 = r & 63;
            float freq  = powf(10000.0f, -(float)d2 / 64.0f);
            float sn, cs;
            sincosf((float)s * freq, &sn, &cs);
            rope[r] = make_float2(cs, sn);
        }
        return;
    }

    const float* in;
    __half* out;
    if (i < n8x) { in = x; out = xt; }
    else if (i < n8x + n8q) { in = wq; out = wqh; i -= n8x; }
    else { in = wo; out = woh; i -= n8x + n8q; }

    float4 v0 = ((const float4*)in)[2 * i];
    float4 v1 = ((const float4*)in)[2 * i + 1];
    __half2 h0 = __floats2half2_rn(v0.x, v0.y);
    __half2 h1 = __floats2half2_rn(v0.z, v0.w);
    __half2 h2 = __floats2half2_rn(v1.x, v1.y);
    __half2 h3 = __floats2half2_rn(v1.z, v1.w);
    uint4 u;
    u.x = *(uint32_t*)&h0; u.y = *(uint32_t*)&h1;
    u.z = *(uint32_t*)&h2; u.w = *(uint32_t*)&h3;
    ((uint4*)out)[i] = u;
}

// ---------------------------------------------------------------------------
// fp16 mma GEMM with ldmatrix fragments. (R13 core; RoPE via table lookup)
// CTA 128x128, 256 threads = 8 warps (2m x 4n), warp tile 64x32.
// KC=64 halves, 3 stages, stride-72-half smem. 2 CTAs/SM.
// ---------------------------------------------------------------------------
#define KC2 64
#define STG 3
#define STRH 72
#define ATILE_H (128 * STRH)
#define STAGE_H (2 * ATILE_H)
#define GEMM2_SMEM (STG * STAGE_H * 2)        // 110592 bytes

__global__ void __launch_bounds__(256, 2) mma_gemm_h(
    const __half* __restrict__ A, const __half* __restrict__ W,
    const float* __restrict__ bias, float* __restrict__ Cf,
    __half* __restrict__ Ch, const float2* __restrict__ rope,
    int M, int N, int K, int qkv_mode)
{
    extern __shared__ __half smh[];
    const int tid = threadIdx.x;
    const int wid = tid >> 5;
    const int lid = tid & 31;
    const int g   = lid >> 2;
    const int tg  = lid & 3;
    const int wm  = wid >> 2;
    const int wn  = wid & 3;
    const int m0 = blockIdx.y << 7;
    const int n0 = blockIdx.x << 7;

    const int i4 = lid >> 3;
    const int j8 = lid & 7;
    const int a_r = (i4 & 1) * 8 + j8;
    const int a_c = (i4 >> 1) * 8;
    const int b_r = (i4 >> 1) * 8 + j8;
    const int b_c = (i4 & 1) * 8;

    const __half* Abase = A + (size_t)m0 * K;
    const __half* Wbase = W + (size_t)n0 * K;

    float acc[4][4][4];
#pragma unroll
    for (int mi = 0; mi < 4; mi++)
#pragma unroll
        for (int ni = 0; ni < 4; ni++)
#pragma unroll
            for (int r = 0; r < 4; r++) acc[mi][ni][r] = 0.f;

    const int nc = K / KC2;

    auto issue_load = [&](int stage, int chunk) {
        const int k0 = chunk * KC2;
        __half* As = smh + stage * STAGE_H;
        __half* Bs = As + ATILE_H;
#pragma unroll
        for (int i = 0; i < 4; i++) {
            const int idx = i * 256 + tid;
            const int row = idx >> 3;
            const int s8  = (idx & 7) << 3;
            cp16(&As[row * STRH + s8], Abase + (size_t)row * K + k0 + s8);
            cp16(&Bs[row * STRH + s8], Wbase + (size_t)row * K + k0 + s8);
        }
    };

    auto compute = [&](int stage) {
        const __half* As = smh + stage * STAGE_H;
        const __half* Bs = As + ATILE_H;
#pragma unroll
        for (int ks = 0; ks < 4; ks++) {
            const int kc = ks * 16;
            uint32_t bf[4][2];
#pragma unroll
            for (int nip = 0; nip < 2; nip++) {
                uint32_t r0, r1, r2, r3;
                ldsm4(r0, r1, r2, r3,
                      &Bs[(wn * 32 + nip * 16 + b_r) * STRH + kc + b_c]);
                bf[2 * nip][0]     = r0; bf[2 * nip][1]     = r1;
                bf[2 * nip + 1][0] = r2; bf[2 * nip + 1][1] = r3;
            }
#pragma unroll
            for (int mi = 0; mi < 4; mi++) {
                uint32_t a0, a1, a2, a3;
                ldsm4(a0, a1, a2, a3,
                      &As[(wm * 64 + mi * 16 + a_r) * STRH + kc + a_c]);
#pragma unroll
                for (int ni = 0; ni < 4; ni++)
                    mma_f16(acc[mi][ni], a0, a1, a2, a3,
                            bf[ni][0], bf[ni][1]);
            }
        }
    };

#pragma unroll
    for (int s = 0; s < STG - 1; s++) {
        issue_load(s, s);
        CP_COMMIT();
    }

    int st = 0;
    for (int c = 0; c < nc; c++) {
        CP_WAIT(STG - 2);
        __syncthreads();
        const int nxt = c + STG - 1;
        if (nxt < nc) {
            int nst = st + STG - 1; if (nst >= STG) nst -= STG;
            issue_load(nst, nxt);
        }
        CP_COMMIT();
        compute(st);
        if (++st == STG) st = 0;
    }

    const bool do_rope = qkv_mode && (n0 < 2 * Dn);
    const float qs = (qkv_mode && n0 < Dn) ? ATTN_SCALE : 1.0f;
#pragma unroll
    for (int ni = 0; ni < 4; ni++) {
        const int col = n0 + wn * 32 + ni * 8 + 2 * tg;
        const float2 bj = *(const float2*)&bias[col];
        const int d2 = (col & 127) >> 1;
#pragma unroll
        for (int mi = 0; mi < 4; mi++) {
            const int row = m0 + wm * 64 + mi * 16 + g;
            float2 o0, o1;
            o0.x = acc[mi][ni][0] + bj.x;
            o0.y = acc[mi][ni][1] + bj.y;
            o1.x = acc[mi][ni][2] + bj.x;
            o1.y = acc[mi][ni][3] + bj.y;
            if (do_rope) {
                float2 cs0 = rope[((row) & (Sn - 1)) * 64 + d2];
                float2 cs1 = rope[((row + 8) & (Sn - 1)) * 64 + d2];
                float r0x = o0.x * cs0.x - o0.y * cs0.y;
                float r0y = o0.x * cs0.y + o0.y * cs0.x;
                o0.x = r0x; o0.y = r0y;
                float r1x = o1.x * cs1.x - o1.y * cs1.y;
                float r1y = o1.x * cs1.y + o1.y * cs1.x;
                o1.x = r1x; o1.y = r1y;
            }
            if (qkv_mode) {
                __half2 h0 = __floats2half2_rn(o0.x * qs, o0.y * qs);
                __half2 h1 = __floats2half2_rn(o1.x * qs, o1.y * qs);
                *(__half2*)&Ch[(size_t)row * N + col] = h0;
                *(__half2*)&Ch[(size_t)(row + 8) * N + col] = h1;
            } else {
                *(float2*)&Cf[(size_t)row * N + col] = o0;
                *(float2*)&Cf[(size_t)(row + 8) * N + col] = o1;
            }
        }
    }
}

// ---------------------------------------------------------------------------
// Tensor-core flash attention (causal), fp16 mma m16n8k16.
// 128 threads/CTA, 64 q-rows, 4 warps x 16 rows -> 3 CTAs/SM.
// LPT scheduling: longest CTAs (largest qb) launch first.
// ---------------------------------------------------------------------------
#define KSTR_H 136
#define PSTR_H 136
#define FA_SMEM ((64 * KSTR_H * 3) * 2)   // 52224 B

__global__ void __launch_bounds__(128, 3) flash_attn_tc(
    const __half* __restrict__ qkv, __half* __restrict__ Y)
{
    extern __shared__ __half smh[];
    __half* Ks = smh;
    __half* Vs = Ks + 64 * KSTR_H;
    __half* Pw = Vs + 64 * KSTR_H;

    const int tid = threadIdx.x;
    const int wid = tid >> 5;
    const int lid = tid & 31;
    const int g   = lid >> 2;
    const int tg  = lid & 3;
    const int qb  = (int)gridDim.x - 1 - (int)blockIdx.x;   // LPT order
    const int q0  = qb * 64;
    const int bh  = blockIdx.y;
    const int b   = bh >> 4;
    const int h   = bh & 15;

    const int row0 = q0 + wid * 16 + g;

    const int i4 = lid >> 3;
    const int j8 = lid & 7;
    const int b_r = (i4 >> 1) * 8 + j8;
    const int b_c = (i4 & 1) * 8;

    const __half* qptr = qkv + ((size_t)(b * Sn + row0)) * TDn + h * DHn;
    uint32_t qf[8][4];
#pragma unroll
    for (int kt = 0; kt < 8; kt++) {
        qf[kt][0] = *(const uint32_t*)(qptr + kt * 16 + 2 * tg);
        qf[kt][1] = *(const uint32_t*)(qptr + (size_t)8 * TDn + kt * 16 + 2 * tg);
        qf[kt][2] = *(const uint32_t*)(qptr + kt * 16 + 8 + 2 * tg);
        qf[kt][3] = *(const uint32_t*)(qptr + (size_t)8 * TDn + kt * 16 + 8 + 2 * tg);
    }

    float ofr[16][4];
#pragma unroll
    for (int nt = 0; nt < 16; nt++)
#pragma unroll
        for (int r = 0; r < 4; r++) ofr[nt][r] = 0.f;

    float m0 = -1e30f, m1 = -1e30f, l0 = 0.f, l1 = 0.f;

    const __half* kbase = qkv + ((size_t)(b * Sn)) * TDn + Dn + h * DHn;
    const __half* vbase = kbase + Dn;
    __half* prow = Pw + (wid * 16) * PSTR_H;

    const int ldi = lid >> 3;
    const int ldj = lid & 7;

    const int nkb = qb + 1;
    for (int kb = 0; kb < nkb; kb++) {
        __syncthreads();
        const int k0 = kb * 64;

#pragma unroll
        for (int i = 0; i < 8; i++) {
            int idx = tid + i * 128;
            int r  = idx >> 4;
            int s8 = (idx & 15) << 3;
            const size_t go = (size_t)(k0 + r) * TDn + s8;
            *(uint4*)&Ks[r * KSTR_H + s8] = *(const uint4*)(kbase + go);
            *(uint4*)&Vs[r * KSTR_H + s8] = *(const uint4*)(vbase + go);
        }
        __syncthreads();

        float sc[8][4];
#pragma unroll
        for (int nt = 0; nt < 8; nt++)
#pragma unroll
            for (int r = 0; r < 4; r++) sc[nt][r] = 0.f;

#pragma unroll
        for (int kt = 0; kt < 8; kt++) {
            uint32_t bf[8][2];
#pragma unroll
            for (int ntp = 0; ntp < 4; ntp++) {
                uint32_t r0, r1, r2, r3;
                ldsm4(r0, r1, r2, r3,
                      &Ks[(ntp * 16 + b_r) * KSTR_H + kt * 16 + b_c]);
                bf[2 * ntp][0]     = r0; bf[2 * ntp][1]     = r1;
                bf[2 * ntp + 1][0] = r2; bf[2 * ntp + 1][1] = r3;
            }
#pragma unroll
            for (int nt = 0; nt < 8; nt++)
                mma_f16(sc[nt], qf[kt][0], qf[kt][1], qf[kt][2], qf[kt][3],
                        bf[nt][0], bf[nt][1]);
        }

        if (kb == qb) {
#pragma unroll
            for (int nt = 0; nt < 8; nt++) {
                int col = k0 + nt * 8 + 2 * tg;
                if (col > row0)     sc[nt][0] = -1e30f;
                if (col + 1 > row0) sc[nt][1] = -1e30f;
                if (col > row0 + 8)     sc[nt][2] = -1e30f;
                if (col + 1 > row0 + 8) sc[nt][3] = -1e30f;
            }
        }

        float mx0 = -1e30f, mx1 = -1e30f;
#pragma unroll
        for (int nt = 0; nt < 8; nt++) {
            mx0 = fmaxf(mx0, fmaxf(sc[nt][0], sc[nt][1]));
            mx1 = fmaxf(mx1, fmaxf(sc[nt][2], sc[nt][3]));
        }
        mx0 = fmaxf(mx0, __shfl_xor_sync(0xffffffffu, mx0, 1));
        mx0 = fmaxf(mx0, __shfl_xor_sync(0xffffffffu, mx0, 2));
        mx1 = fmaxf(mx1, __shfl_xor_sync(0xffffffffu, mx1, 1));
        mx1 = fmaxf(mx1, __shfl_xor_sync(0xffffffffu, mx1, 2));

        const float mn0 = fmaxf(m0, mx0);
        const float mn1 = fmaxf(m1, mx1);
        const float a0 = __expf(m0 - mn0);
        const float a1 = __expf(m1 - mn1);
        m0 = mn0; m1 = mn1;

        float s0 = 0.f, s1 = 0.f;
#pragma unroll
        for (int nt = 0; nt < 8; nt++) {
            sc[nt][0] = __expf(sc[nt][0] - mn0);
            sc[nt][1] = __expf(sc[nt][1] - mn0);
            sc[nt][2] = __expf(sc[nt][2] - mn1);
            sc[nt][3] = __expf(sc[nt][3] - mn1);
            s0 += sc[nt][0] + sc[nt][1];
            s1 += sc[nt][2] + sc[nt][3];
        }
        s0 += __shfl_xor_sync(0xffffffffu, s0, 1);
        s0 += __shfl_xor_sync(0xffffffffu, s0, 2);
        s1 += __shfl_xor_sync(0xffffffffu, s1, 1);
        s1 += __shfl_xor_sync(0xffffffffu, s1, 2);
        l0 = l0 * a0 + s0;
        l1 = l1 * a1 + s1;

#pragma unroll
        for (int nt = 0; nt < 16; nt++) {
            ofr[nt][0] *= a0; ofr[nt][1] *= a0;
            ofr[nt][2] *= a1; ofr[nt][3] *= a1;
        }

        __syncwarp();
#pragma unroll
        for (int nt = 0; nt < 8; nt++) {
            const int col = nt * 8 + 2 * tg;
            *(__half2*)&prow[g * PSTR_H + col] =
                __floats2half2_rn(sc[nt][0], sc[nt][1]);
            *(__half2*)&prow[(g + 8) * PSTR_H + col] =
                __floats2half2_rn(sc[nt][2], sc[nt][3]);
        }
        __syncwarp();

#pragma unroll
        for (int kt = 0; kt < 4; kt++) {
            uint32_t pa0 = *(const uint32_t*)&prow[g * PSTR_H + kt * 16 + 2 * tg];
            uint32_t pa1 = *(const uint32_t*)&prow[(g + 8) * PSTR_H + kt * 16 + 2 * tg];
            uint32_t pa2 = *(const uint32_t*)&prow[g * PSTR_H + kt * 16 + 8 + 2 * tg];
            uint32_t pa3 = *(const uint32_t*)&prow[(g + 8) * PSTR_H + kt * 16 + 8 + 2 * tg];
            const int vrow = kt * 16 + (ldi & 1) * 8 + ldj;
#pragma unroll
            for (int ntp = 0; ntp < 8; ntp++) {
                uint32_t r0, r1, r2, r3;
                ldsm4t(r0, r1, r2, r3,
                       &Vs[vrow * KSTR_H + ntp * 16 + (ldi >> 1) * 8]);
                mma_f16(ofr[2 * ntp],     pa0, pa1, pa2, pa3, r0, r1);
                mma_f16(ofr[2 * ntp + 1], pa0, pa1, pa2, pa3, r2, r3);
            }
        }
    }

    const float inv0 = 1.0f / l0;
    const float inv1 = 1.0f / l1;
    __half* yrow = Y + ((size_t)(b * Sn + row0)) * Dn + h * DHn;
#pragma unroll
    for (int nt = 0; nt < 16; nt++) {
        const int col = nt * 8 + 2 * tg;
        __half2 h0 = __floats2half2_rn(ofr[nt][0] * inv0, ofr[nt][1] * inv0);
        __half2 h1 = __floats2half2_rn(ofr[nt][2] * inv1, ofr[nt][3] * inv1);
        *(__half2*)&yrow[col] = h0;
        *(__half2*)&yrow[(size_t)8 * Dn + col] = h1;
    }
}

// ---------------------------------------------------------------------------
extern "C" void kernel_launch(void* const* d_in, const int* in_sizes, int n_in,
                              void* d_out, int out_size)
{
    (void)in_sizes; (void)n_in; (void)out_size;
    const float* x      = (const float*)d_in[0];
    const float* qkv_w  = (const float*)d_in[1];
    const float* qkv_b  = (const float*)d_in[2];
    const float* out_w  = (const float*)d_in[3];
    const float* out_b  = (const float*)d_in[4];
    float* out = (float*)d_out;

    __half *qkv, *y, *xt, *wq, *wo;
    float2* rope;
    cudaGetSymbolAddress((void**)&qkv, g_qkv);
    cudaGetSymbolAddress((void**)&y, g_y);
    cudaGetSymbolAddress((void**)&xt, g_xt);
    cudaGetSymbolAddress((void**)&wq, g_wq);
    cudaGetSymbolAddress((void**)&wo, g_wo);
    cudaGetSymbolAddress((void**)&rope, g_rope);

    cudaFuncSetAttribute(mma_gemm_h,
                         cudaFuncAttributeMaxDynamicSharedMemorySize, GEMM2_SMEM);
    cudaFuncSetAttribute(flash_attn_tc,
                         cudaFuncAttributeMaxDynamicSharedMemorySize, FA_SMEM);

    // 0) Pre-convert inputs to fp16 + build RoPE table (single launch)
    {
        int n8x = (NROWS * Dn) / 8;
        int n8q = (TDn * Dn) / 8;
        int n8o = (Dn * Dn) / 8;
        int total = n8x + n8q + n8o + ROPE_N;
        conv_all_kernel<<<(total + 255) / 256, 256>>>(x, xt, n8x,
                                                      qkv_w, wq, n8q,
                                                      out_w, wo, n8o,
                                                      rope);
    }

    // 1) QKV projection + fused RoPE (table) + q-scale, half output
    {
        dim3 grid(TDn / 128, NROWS / 128);
        mma_gemm_h<<<grid, 256, GEMM2_SMEM>>>(xt, wq, qkv_b, nullptr, qkv,
                                              rope, NROWS, TDn, Dn, 1);
    }

    // 2) Flash attention (fp16 mma, 64-row CTAs, LPT order), emits half y
    {
        dim3 grid(Sn / 64, Bn * Hn);
        flash_attn_tc<<<grid, 128, FA_SMEM>>>(qkv, y);
    }

    // 3) Output projection (fp16 mma, fp32 output)
    {
        dim3 grid(Dn / 128, NROWS / 128);
        mma_gemm_h<<<grid, 256, GEMM2_SMEM>>>(y, wo, out_b, out, nullptr,
                                              rope, NROWS, Dn, Dn, 0);
    }
}

// round 17
// speedup vs baseline: 1.0223x; 1.0223x over previous
#include <cuda_runtime.h>
#include <cuda_fp16.h>
#include <cstdint>
#include <math.h>

// Problem constants
#define Bn 4
#define Sn 2048
#define Dn 2048
#define Hn 16
#define DHn 128
#define TDn 6144            // 3*D
#define NROWS (Bn*Sn)       // 8192

#define ATTN_SCALE 0.08838834764831845f

// Scratch (device globals; no cudaMalloc allowed)
__device__ __half g_qkv[(size_t)NROWS * TDn];   // 100 MB half (RoPE'd, q scaled)
__device__ __half g_y[(size_t)NROWS * Dn];      // 33 MB  half (attn out)
__device__ __half g_xt[(size_t)NROWS * Dn];     // 33 MB  x  half
__device__ __half g_wq[(size_t)TDn * Dn];       // 25 MB  qkv_w half
__device__ __half g_wo[(size_t)Dn * Dn];        // 8 MB   out_w half

__device__ __forceinline__ void mma_f16(float* d,
                                        uint32_t a0, uint32_t a1,
                                        uint32_t a2, uint32_t a3,
                                        uint32_t b0, uint32_t b1) {
    asm volatile(
        "mma.sync.aligned.m16n8k16.row.col.f32.f16.f16.f32 "
        "{%0,%1,%2,%3}, {%4,%5,%6,%7}, {%8,%9}, {%0,%1,%2,%3};"
        : "+f"(d[0]), "+f"(d[1]), "+f"(d[2]), "+f"(d[3])
        : "r"(a0), "r"(a1), "r"(a2), "r"(a3), "r"(b0), "r"(b1));
}

__device__ __forceinline__ void ldsm4(uint32_t& r0, uint32_t& r1,
                                      uint32_t& r2, uint32_t& r3,
                                      const __half* p) {
    uint32_t a = (uint32_t)__cvta_generic_to_shared(p);
    asm volatile(
        "ldmatrix.sync.aligned.m8n8.x4.shared.b16 {%0,%1,%2,%3}, [%4];"
        : "=r"(r0), "=r"(r1), "=r"(r2), "=r"(r3) : "r"(a));
}

__device__ __forceinline__ void ldsm4t(uint32_t& r0, uint32_t& r1,
                                       uint32_t& r2, uint32_t& r3,
                                       const __half* p) {
    uint32_t a = (uint32_t)__cvta_generic_to_shared(p);
    asm volatile(
        "ldmatrix.sync.aligned.m8n8.x4.trans.shared.b16 {%0,%1,%2,%3}, [%4];"
        : "=r"(r0), "=r"(r1), "=r"(r2), "=r"(r3) : "r"(a));
}

__device__ __forceinline__ void cp16(void* smem_ptr, const void* gptr) {
    uint32_t sa = (uint32_t)__cvta_generic_to_shared(smem_ptr);
    asm volatile("cp.async.cg.shared.global [%0], [%1], 16;"
                 :: "r"(sa), "l"(gptr));
}
#define CP_COMMIT() asm volatile("cp.async.commit_group;" ::: "memory")
#define CP_WAIT(n)  asm volatile("cp.async.wait_group %0;" :: "n"(n) : "memory")

// ---------------------------------------------------------------------------
// Pre-convert fp32 -> fp16, all three inputs in ONE launch (segmented).
// ---------------------------------------------------------------------------
__global__ __launch_bounds__(256) void conv_all_kernel(
    const float* __restrict__ x,  __half* __restrict__ xt,  int n8x,
    const float* __restrict__ wq, __half* __restrict__ wqh, int n8q,
    const float* __restrict__ wo, __half* __restrict__ woh, int n8o)
{
    int i = blockIdx.x * blockDim.x + threadIdx.x;
    const float* in;
    __half* out;
    if (i < n8x) { in = x; out = xt; }
    else if (i < n8x + n8q) { in = wq; out = wqh; i -= n8x; }
    else if (i < n8x + n8q + n8o) { in = wo; out = woh; i -= n8x + n8q; }
    else return;

    float4 v0 = ((const float4*)in)[2 * i];
    float4 v1 = ((const float4*)in)[2 * i + 1];
    __half2 h0 = __floats2half2_rn(v0.x, v0.y);
    __half2 h1 = __floats2half2_rn(v0.z, v0.w);
    __half2 h2 = __floats2half2_rn(v1.x, v1.y);
    __half2 h3 = __floats2half2_rn(v1.z, v1.w);
    uint4 u;
    u.x = *(uint32_t*)&h0; u.y = *(uint32_t*)&h1;
    u.z = *(uint32_t*)&h2; u.w = *(uint32_t*)&h3;
    ((uint4*)out)[i] = u;
}

// ---------------------------------------------------------------------------
// fp16 mma GEMM with ldmatrix fragments. (R15-proven, untouched)
// CTA 128x128, 256 threads = 8 warps (2m x 4n), warp tile 64x32.
// KC=64 halves, 3 stages, stride-72-half smem. 2 CTAs/SM.
// ---------------------------------------------------------------------------
#define KC2 64
#define STG 3
#define STRH 72
#define ATILE_H (128 * STRH)
#define STAGE_H (2 * ATILE_H)
#define GEMM2_SMEM (STG * STAGE_H * 2)        // 110592 bytes

__global__ void __launch_bounds__(256, 2) mma_gemm_h(
    const __half* __restrict__ A, const __half* __restrict__ W,
    const float* __restrict__ bias, float* __restrict__ Cf,
    __half* __restrict__ Ch,
    int M, int N, int K, int qkv_mode)
{
    extern __shared__ __half smh[];
    const int tid = threadIdx.x;
    const int wid = tid >> 5;
    const int lid = tid & 31;
    const int g   = lid >> 2;
    const int tg  = lid & 3;
    const int wm  = wid >> 2;
    const int wn  = wid & 3;
    const int m0 = blockIdx.y << 7;
    const int n0 = blockIdx.x << 7;

    const int i4 = lid >> 3;
    const int j8 = lid & 7;
    const int a_r = (i4 & 1) * 8 + j8;
    const int a_c = (i4 >> 1) * 8;
    const int b_r = (i4 >> 1) * 8 + j8;
    const int b_c = (i4 & 1) * 8;

    const __half* Abase = A + (size_t)m0 * K;
    const __half* Wbase = W + (size_t)n0 * K;

    float acc[4][4][4];
#pragma unroll
    for (int mi = 0; mi < 4; mi++)
#pragma unroll
        for (int ni = 0; ni < 4; ni++)
#pragma unroll
            for (int r = 0; r < 4; r++) acc[mi][ni][r] = 0.f;

    const int nc = K / KC2;

    auto issue_load = [&](int stage, int chunk) {
        const int k0 = chunk * KC2;
        __half* As = smh + stage * STAGE_H;
        __half* Bs = As + ATILE_H;
#pragma unroll
        for (int i = 0; i < 4; i++) {
            const int idx = i * 256 + tid;
            const int row = idx >> 3;
            const int s8  = (idx & 7) << 3;
            cp16(&As[row * STRH + s8], Abase + (size_t)row * K + k0 + s8);
            cp16(&Bs[row * STRH + s8], Wbase + (size_t)row * K + k0 + s8);
        }
    };

    auto compute = [&](int stage) {
        const __half* As = smh + stage * STAGE_H;
        const __half* Bs = As + ATILE_H;
#pragma unroll
        for (int ks = 0; ks < 4; ks++) {
            const int kc = ks * 16;
            uint32_t bf[4][2];
#pragma unroll
            for (int nip = 0; nip < 2; nip++) {
                uint32_t r0, r1, r2, r3;
                ldsm4(r0, r1, r2, r3,
                      &Bs[(wn * 32 + nip * 16 + b_r) * STRH + kc + b_c]);
                bf[2 * nip][0]     = r0; bf[2 * nip][1]     = r1;
                bf[2 * nip + 1][0] = r2; bf[2 * nip + 1][1] = r3;
            }
#pragma unroll
            for (int mi = 0; mi < 4; mi++) {
                uint32_t a0, a1, a2, a3;
                ldsm4(a0, a1, a2, a3,
                      &As[(wm * 64 + mi * 16 + a_r) * STRH + kc + a_c]);
#pragma unroll
                for (int ni = 0; ni < 4; ni++)
                    mma_f16(acc[mi][ni], a0, a1, a2, a3,
                            bf[ni][0], bf[ni][1]);
            }
        }
    };

#pragma unroll
    for (int s = 0; s < STG - 1; s++) {
        issue_load(s, s);
        CP_COMMIT();
    }

    int st = 0;
    for (int c = 0; c < nc; c++) {
        CP_WAIT(STG - 2);
        __syncthreads();
        const int nxt = c + STG - 1;
        if (nxt < nc) {
            int nst = st + STG - 1; if (nst >= STG) nst -= STG;
            issue_load(nst, nxt);
        }
        CP_COMMIT();
        compute(st);
        if (++st == STG) st = 0;
    }

    const bool do_rope = qkv_mode && (n0 < 2 * Dn);
    const float qs = (qkv_mode && n0 < Dn) ? ATTN_SCALE : 1.0f;
#pragma unroll
    for (int ni = 0; ni < 4; ni++) {
        const int col = n0 + wn * 32 + ni * 8 + 2 * tg;
        const float2 bj = *(const float2*)&bias[col];
        float freq = 0.f;
        if (do_rope) {
            const int d2 = (col & 127) >> 1;
            freq = powf(10000.0f, -(float)d2 / 64.0f);
        }
#pragma unroll
        for (int mi = 0; mi < 4; mi++) {
            const int row = m0 + wm * 64 + mi * 16 + g;
            float2 o0, o1;
            o0.x = acc[mi][ni][0] + bj.x;
            o0.y = acc[mi][ni][1] + bj.y;
            o1.x = acc[mi][ni][2] + bj.x;
            o1.y = acc[mi][ni][3] + bj.y;
            if (do_rope) {
                float sn, cs;
                float omega = (float)(row & (Sn - 1)) * freq;
                sincosf(omega, &sn, &cs);
                float r0x = o0.x * cs - o0.y * sn;
                float r0y = o0.x * sn + o0.y * cs;
                o0.x = r0x; o0.y = r0y;
                omega = (float)((row + 8) & (Sn - 1)) * freq;
                sincosf(omega, &sn, &cs);
                float r1x = o1.x * cs - o1.y * sn;
                float r1y = o1.x * sn + o1.y * cs;
                o1.x = r1x; o1.y = r1y;
            }
            if (qkv_mode) {
                __half2 h0 = __floats2half2_rn(o0.x * qs, o0.y * qs);
                __half2 h1 = __floats2half2_rn(o1.x * qs, o1.y * qs);
                *(__half2*)&Ch[(size_t)row * N + col] = h0;
                *(__half2*)&Ch[(size_t)(row + 8) * N + col] = h1;
            } else {
                *(float2*)&Cf[(size_t)row * N + col] = o0;
                *(float2*)&Cf[(size_t)(row + 8) * N + col] = o1;
            }
        }
    }
}

// ---------------------------------------------------------------------------
// Tensor-core flash attention (causal), fp16 mma m16n8k16.
// 128 threads/CTA, 64 q-rows, 4 warps x 16 rows, 3 CTAs/SM.
// P stays in REGISTERS: S C-fragment layout == PV A-fragment layout.
// ---------------------------------------------------------------------------
#define KSTR_H 136
#define FA_SMEM ((64 * KSTR_H * 2) * 2)   // Ks + Vs = 34816 B

__global__ void __launch_bounds__(128, 3) flash_attn_tc(
    const __half* __restrict__ qkv, __half* __restrict__ Y)
{
    extern __shared__ __half smh[];
    __half* Ks = smh;
    __half* Vs = Ks + 64 * KSTR_H;

    const int tid = threadIdx.x;
    const int wid = tid >> 5;          // 0..3
    const int lid = tid & 31;
    const int g   = lid >> 2;
    const int tg  = lid & 3;
    const int qb  = blockIdx.x;
    const int q0  = qb * 64;
    const int bh  = blockIdx.y;
    const int b   = bh >> 4;
    const int h   = bh & 15;

    const int row0 = q0 + wid * 16 + g;

    // ldmatrix lane addressing (B operand, non-trans)
    const int i4 = lid >> 3;
    const int j8 = lid & 7;
    const int b_r = (i4 >> 1) * 8 + j8;
    const int b_c = (i4 & 1) * 8;

    const __half* qptr = qkv + ((size_t)(b * Sn + row0)) * TDn + h * DHn;
    uint32_t qf[8][4];
#pragma unroll
    for (int kt = 0; kt < 8; kt++) {
        qf[kt][0] = *(const uint32_t*)(qptr + kt * 16 + 2 * tg);
        qf[kt][1] = *(const uint32_t*)(qptr + (size_t)8 * TDn + kt * 16 + 2 * tg);
        qf[kt][2] = *(const uint32_t*)(qptr + kt * 16 + 8 + 2 * tg);
        qf[kt][3] = *(const uint32_t*)(qptr + (size_t)8 * TDn + kt * 16 + 8 + 2 * tg);
    }

    float ofr[16][4];
#pragma unroll
    for (int nt = 0; nt < 16; nt++)
#pragma unroll
        for (int r = 0; r < 4; r++) ofr[nt][r] = 0.f;

    float m0 = -1e30f, m1 = -1e30f, l0 = 0.f, l1 = 0.f;

    const __half* kbase = qkv + ((size_t)(b * Sn)) * TDn + Dn + h * DHn;
    const __half* vbase = kbase + Dn;

    const int ldi = lid >> 3;
    const int ldj = lid & 7;

    const int nkb = qb + 1;
    for (int kb = 0; kb < nkb; kb++) {
        __syncthreads();
        const int k0 = kb * 64;

        // Load K,V tiles: 64 rows x 128 halves each
#pragma unroll
        for (int i = 0; i < 8; i++) {
            int idx = tid + i * 128;
            int r  = idx >> 4;
            int s8 = (idx & 15) << 3;
            const size_t go = (size_t)(k0 + r) * TDn + s8;
            *(uint4*)&Ks[r * KSTR_H + s8] = *(const uint4*)(kbase + go);
            *(uint4*)&Vs[r * KSTR_H + s8] = *(const uint4*)(vbase + go);
        }
        __syncthreads();

        // S = Q K^T : K B-frags via ldmatrix.x4 (non-trans)
        float sc[8][4];
#pragma unroll
        for (int nt = 0; nt < 8; nt++)
#pragma unroll
            for (int r = 0; r < 4; r++) sc[nt][r] = 0.f;

#pragma unroll
        for (int kt = 0; kt < 8; kt++) {
            uint32_t bf[8][2];
#pragma unroll
            for (int ntp = 0; ntp < 4; ntp++) {
                uint32_t r0, r1, r2, r3;
                ldsm4(r0, r1, r2, r3,
                      &Ks[(ntp * 16 + b_r) * KSTR_H + kt * 16 + b_c]);
                bf[2 * ntp][0]     = r0; bf[2 * ntp][1]     = r1;
                bf[2 * ntp + 1][0] = r2; bf[2 * ntp + 1][1] = r3;
            }
#pragma unroll
            for (int nt = 0; nt < 8; nt++)
                mma_f16(sc[nt], qf[kt][0], qf[kt][1], qf[kt][2], qf[kt][3],
                        bf[nt][0], bf[nt][1]);
        }

        // Causal mask (only last k-tile can violate)
        if (kb == qb) {
#pragma unroll
            for (int nt = 0; nt < 8; nt++) {
                int col = k0 + nt * 8 + 2 * tg;
                if (col > row0)     sc[nt][0] = -1e30f;
                if (col + 1 > row0) sc[nt][1] = -1e30f;
                if (col > row0 + 8)     sc[nt][2] = -1e30f;
                if (col + 1 > row0 + 8) sc[nt][3] = -1e30f;
            }
        }

        // Online softmax
        float mx0 = -1e30f, mx1 = -1e30f;
#pragma unroll
        for (int nt = 0; nt < 8; nt++) {
            mx0 = fmaxf(mx0, fmaxf(sc[nt][0], sc[nt][1]));
            mx1 = fmaxf(mx1, fmaxf(sc[nt][2], sc[nt][3]));
        }
        mx0 = fmaxf(mx0, __shfl_xor_sync(0xffffffffu, mx0, 1));
        mx0 = fmaxf(mx0, __shfl_xor_sync(0xffffffffu, mx0, 2));
        mx1 = fmaxf(mx1, __shfl_xor_sync(0xffffffffu, mx1, 1));
        mx1 = fmaxf(mx1, __shfl_xor_sync(0xffffffffu, mx1, 2));

        const float mn0 = fmaxf(m0, mx0);
        const float mn1 = fmaxf(m1, mx1);
        const float a0 = __expf(m0 - mn0);
        const float a1 = __expf(m1 - mn1);
        m0 = mn0; m1 = mn1;

        float s0 = 0.f, s1 = 0.f;
#pragma unroll
        for (int nt = 0; nt < 8; nt++) {
            sc[nt][0] = __expf(sc[nt][0] - mn0);
            sc[nt][1] = __expf(sc[nt][1] - mn0);
            sc[nt][2] = __expf(sc[nt][2] - mn1);
            sc[nt][3] = __expf(sc[nt][3] - mn1);
            s0 += sc[nt][0] + sc[nt][1];
            s1 += sc[nt][2] + sc[nt][3];
        }
        s0 += __shfl_xor_sync(0xffffffffu, s0, 1);
        s0 += __shfl_xor_sync(0xffffffffu, s0, 2);
        s1 += __shfl_xor_sync(0xffffffffu, s1, 1);
        s1 += __shfl_xor_sync(0xffffffffu, s1, 2);
        l0 = l0 * a0 + s0;
        l1 = l1 * a1 + s1;

#pragma unroll
        for (int nt = 0; nt < 16; nt++) {
            ofr[nt][0] *= a0; ofr[nt][1] *= a0;
            ofr[nt][2] *= a1; ofr[nt][3] *= a1;
        }

        // O += P @ V : P A-frags packed directly from sc (register-resident).
        // C-frag(S) layout == A-frag(PV) layout:
        //   a0=(g, k=2tg),(.,+1)  a1=(g+8, k=2tg)  a2=(g, k=2tg+8)  a3=(g+8, k=2tg+8)
#pragma unroll
        for (int kt = 0; kt < 4; kt++) {
            __half2 ha0 = __floats2half2_rn(sc[2 * kt][0],     sc[2 * kt][1]);
            __half2 ha1 = __floats2half2_rn(sc[2 * kt][2],     sc[2 * kt][3]);
            __half2 ha2 = __floats2half2_rn(sc[2 * kt + 1][0], sc[2 * kt + 1][1]);
            __half2 ha3 = __floats2half2_rn(sc[2 * kt + 1][2], sc[2 * kt + 1][3]);
            uint32_t pa0 = *(uint32_t*)&ha0;
            uint32_t pa1 = *(uint32_t*)&ha1;
            uint32_t pa2 = *(uint32_t*)&ha2;
            uint32_t pa3 = *(uint32_t*)&ha3;
            const int vrow = kt * 16 + (ldi & 1) * 8 + ldj;
#pragma unroll
            for (int ntp = 0; ntp < 8; ntp++) {
                uint32_t r0, r1, r2, r3;
                ldsm4t(r0, r1, r2, r3,
                       &Vs[vrow * KSTR_H + ntp * 16 + (ldi >> 1) * 8]);
                mma_f16(ofr[2 * ntp],     pa0, pa1, pa2, pa3, r0, r1);
                mma_f16(ofr[2 * ntp + 1], pa0, pa1, pa2, pa3, r2, r3);
            }
        }
    }

    const float inv0 = 1.0f / l0;
    const float inv1 = 1.0f / l1;
    __half* yrow = Y + ((size_t)(b * Sn + row0)) * Dn + h * DHn;
#pragma unroll
    for (int nt = 0; nt < 16; nt++) {
        const int col = nt * 8 + 2 * tg;
        __half2 h0 = __floats2half2_rn(ofr[nt][0] * inv0, ofr[nt][1] * inv0);
        __half2 h1 = __floats2half2_rn(ofr[nt][2] * inv1, ofr[nt][3] * inv1);
        *(__half2*)&yrow[col] = h0;
        *(__half2*)&yrow[(size_t)8 * Dn + col] = h1;
    }
}

// ---------------------------------------------------------------------------
extern "C" void kernel_launch(void* const* d_in, const int* in_sizes, int n_in,
                              void* d_out, int out_size)
{
    (void)in_sizes; (void)n_in; (void)out_size;
    const float* x      = (const float*)d_in[0];
    const float* qkv_w  = (const float*)d_in[1];
    const float* qkv_b  = (const float*)d_in[2];
    const float* out_w  = (const float*)d_in[3];
    const float* out_b  = (const float*)d_in[4];
    float* out = (float*)d_out;

    __half *qkv, *y, *xt, *wq, *wo;
    cudaGetSymbolAddress((void**)&qkv, g_qkv);
    cudaGetSymbolAddress((void**)&y, g_y);
    cudaGetSymbolAddress((void**)&xt, g_xt);
    cudaGetSymbolAddress((void**)&wq, g_wq);
    cudaGetSymbolAddress((void**)&wo, g_wo);

    cudaFuncSetAttribute(mma_gemm_h,
                         cudaFuncAttributeMaxDynamicSharedMemorySize, GEMM2_SMEM);
    cudaFuncSetAttribute(flash_attn_tc,
                         cudaFuncAttributeMaxDynamicSharedMemorySize, FA_SMEM);

    // 0) Pre-convert inputs to fp16 (single launch)
    {
        int n8x = (NROWS * Dn) / 8;
        int n8q = (TDn * Dn) / 8;
        int n8o = (Dn * Dn) / 8;
        int total = n8x + n8q + n8o;
        conv_all_kernel<<<(total + 255) / 256, 256>>>(x, xt, n8x,
                                                      qkv_w, wq, n8q,
                                                      out_w, wo, n8o);
    }

    // 1) QKV projection + fused RoPE + q-scale, half output
    {
        dim3 grid(TDn / 128, NROWS / 128);
        mma_gemm_h<<<grid, 256, GEMM2_SMEM>>>(xt, wq, qkv_b, nullptr, qkv,
                                              NROWS, TDn, Dn, 1);
    }

    // 2) Flash attention (fp16 mma, P in registers), emits half y
    {
        dim3 grid(Sn / 64, Bn * Hn);
        flash_attn_tc<<<grid, 128, FA_SMEM>>>(qkv, y);
    }

    // 3) Output projection (fp16 mma, fp32 output)
    {
        dim3 grid(Dn / 128, NROWS / 128);
        mma_gemm_h<<<grid, 256, GEMM2_SMEM>>>(y, wo, out_b, out, nullptr,
                                              NROWS, Dn, Dn, 0);
    }
}